// round 2
// baseline (speedup 1.0000x reference)
#include <cuda_runtime.h>
#include <cuda_bf16.h>

#define BB 16384
#define MM 8
#define DD 64

// Precomputed fused weights: A[e][c] = sum_d W_o[e,d] * W_v[d,c]
// cvec[e] = 8 * (sum_d W_o[e,d]*b_v[d] + b_o[e])
__device__ float g_A[DD * DD];
__device__ float g_cvec[DD];

__global__ void precompute_kernel(const float* __restrict__ W_v,
                                  const float* __restrict__ b_v,
                                  const float* __restrict__ W_o,
                                  const float* __restrict__ b_o) {
    const int c = blockIdx.x;   // 0..63
    const int e = threadIdx.x;  // 0..63
    float acc = 0.f;
#pragma unroll
    for (int d = 0; d < DD; d++)
        acc = fmaf(W_o[e * DD + d], W_v[d * DD + c], acc);
    g_A[e * DD + c] = acc;
    if (c == 0) {
        float cv = 0.f;
#pragma unroll
        for (int d = 0; d < DD; d++)
            cv = fmaf(W_o[e * DD + d], b_v[d], cv);
        g_cvec[e] = 8.0f * (cv + b_o[e]);
    }
}

// One warp per group; 8 warps (256 threads) per block.
// Each lane owns channels {2*lane, 2*lane+1} as a float2.
__global__ __launch_bounds__(256) void mosan_kernel(
    const float* __restrict__ user_emb,   // [1e6, 64]
    const float* __restrict__ item_emb,   // [1e5, 64]
    const int*   __restrict__ members,    // [B, 8]
    const int*   __restrict__ item_inputs,// [B]
    float*       __restrict__ out)        // [B]
{
    __shared__ float sA[DD * DD];  // 16 KB
    __shared__ float sC[DD];

    for (int i = threadIdx.x; i < DD * DD; i += blockDim.x)
        sA[i] = g_A[i];
    if (threadIdx.x < DD) sC[threadIdx.x] = g_cvec[threadIdx.x];
    __syncthreads();

    const int warp = threadIdx.x >> 5;
    const int lane = threadIdx.x & 31;
    const int b = blockIdx.x * 8 + warp;

    // Group member indices: all lanes read the same 8 ints (L1 broadcast).
    int midx[MM];
#pragma unroll
    for (int m = 0; m < MM; m++)
        midx[m] = members[b * MM + m];
    const int iidx = item_inputs[b];

    // Issue all 9 row loads before consuming -> MLP = 9 per warp.
    const float2* ue = reinterpret_cast<const float2*>(user_emb);
    const float2* ie = reinterpret_cast<const float2*>(item_emb);
    float2 rows[MM];
#pragma unroll
    for (int m = 0; m < MM; m++)
        rows[m] = ue[(size_t)midx[m] * 32 + lane];
    float2 t = ie[(size_t)iidx * 32 + lane];

    float2 E = make_float2(0.f, 0.f);
#pragma unroll
    for (int m = 0; m < MM; m++) { E.x += rows[m].x; E.y += rows[m].y; }

    // s_c = sum_e t_e * A[e][c] for c in {2*lane, 2*lane+1}
    const float2* sA2 = reinterpret_cast<const float2*>(sA);
    float2 s = make_float2(0.f, 0.f);
#pragma unroll
    for (int src = 0; src < 32; src++) {
        const float tx = __shfl_sync(0xffffffffu, t.x, src);
        const float ty = __shfl_sync(0xffffffffu, t.y, src);
        const float2 a0 = sA2[(2 * src)     * 32 + lane];
        const float2 a1 = sA2[(2 * src + 1) * 32 + lane];
        s.x = fmaf(tx, a0.x, s.x); s.x = fmaf(ty, a1.x, s.x);
        s.y = fmaf(tx, a0.y, s.y); s.y = fmaf(ty, a1.y, s.y);
    }

    float y = s.x * E.x + s.y * E.y
            + sC[2 * lane] * t.x + sC[2 * lane + 1] * t.y;

#pragma unroll
    for (int off = 16; off; off >>= 1)
        y += __shfl_xor_sync(0xffffffffu, y, off);

    if (lane == 0) out[b] = y;
}

extern "C" void kernel_launch(void* const* d_in, const int* in_sizes, int n_in,
                              void* d_out, int out_size) {
    // metadata order:
    // 0 user_emb, 1 quser_emb, 2 item_emb, 3 W_q, 4 b_q, 5 W_k, 6 b_k,
    // 7 W_v, 8 b_v, 9 W_o, 10 b_o, 11 w_t, 12 b_t, 13 members, 14 item_inputs
    const float* user_emb    = (const float*)d_in[0];
    const float* item_emb    = (const float*)d_in[2];
    const float* W_v         = (const float*)d_in[7];
    const float* b_v         = (const float*)d_in[8];
    const float* W_o         = (const float*)d_in[9];
    const float* b_o         = (const float*)d_in[10];
    const int*   members     = (const int*)d_in[13];
    const int*   item_inputs = (const int*)d_in[14];
    float* out = (float*)d_out;

    precompute_kernel<<<DD, DD>>>(W_v, b_v, W_o, b_o);
    mosan_kernel<<<BB / 8, 256>>>(user_emb, item_emb, members, item_inputs, out);
}

// round 4
// speedup vs baseline: 1.4614x; 1.4614x over previous
#include <cuda_runtime.h>
#include <cuda_bf16.h>

#define BB 16384
#define MM 8
#define DD 64
#define GPB 32              // groups per block
#define NBLK (BB / GPB)     // 512 blocks
#define TSS 68              // padded row stride (floats) for Ts/Es

// Fused weights: A[e][c] = sum_d W_o[e,d] * W_v[d,c];  cvec[e] = 8*(W_o·b_v + b_o)[e]
__device__ float g_A[DD * DD];
__device__ float g_cvec[DD];

__global__ __launch_bounds__(256) void precompute_kernel(
    const float* __restrict__ W_v, const float* __restrict__ b_v,
    const float* __restrict__ W_o, const float* __restrict__ b_o) {
    const int idx = blockIdx.x * 256 + threadIdx.x;  // 0..4095
    const int e = idx >> 6, c = idx & 63;
    float acc = 0.f;
#pragma unroll
    for (int d = 0; d < DD; d++)
        acc = fmaf(W_o[e * DD + d], W_v[d * DD + c], acc);
    g_A[idx] = acc;
    if (idx < DD) {
        float cv = 0.f;
#pragma unroll
        for (int d = 0; d < DD; d++)
            cv = fmaf(W_o[idx * DD + d], b_v[d], cv);
        g_cvec[idx] = 8.0f * (cv + b_o[idx]);
    }
}

// 128 threads, 32 groups per block.
// Phase 1 (gather): warp w handles local groups [w*8, w*8+8); lanes split 16/16
//   over two groups at a time; each 16-lane half loads full 256B rows as float4.
// Phase 2 (GEMM): thread (tx,ty) owns 4 groups x 4 channels; s = T·A, y = <s,E> + cdot.
__global__ __launch_bounds__(128) void mosan_kernel(
    const float* __restrict__ user_emb,    // [1e6, 64]
    const float* __restrict__ item_emb,    // [1e5, 64]
    const int*   __restrict__ members,     // [B, 8]
    const int*   __restrict__ item_inputs, // [B]
    float*       __restrict__ out)         // [B]
{
    __shared__ float sA[DD * DD];     // 16 KB, row stride 64
    __shared__ float sTs[GPB * TSS];  // item rows, padded stride
    __shared__ float sEs[GPB * TSS];  // summed member rows
    __shared__ float sCd[GPB];        // cvec . t per group

    const int tid  = threadIdx.x;
    const int lane = tid & 31;
    const int warp = tid >> 5;        // 0..3
    const int gbase = blockIdx.x * GPB;

    // Stage A into shared (from L2-resident g_A).
    {
        const float4* gA4 = reinterpret_cast<const float4*>(g_A);
        float4* sA4 = reinterpret_cast<float4*>(sA);
#pragma unroll
        for (int i = tid; i < DD * DD / 4; i += 128) sA4[i] = gA4[i];
    }

    // ---- Gather phase ----
    const int half = lane >> 4;       // 0/1 -> which group of the pair
    const int hl   = lane & 15;       // channel quad: owns channels 4*hl..4*hl+3
    const float4* ue4 = reinterpret_cast<const float4*>(user_emb);
    const float4* ie4 = reinterpret_cast<const float4*>(item_emb);
    const float4  cv  = reinterpret_cast<const float4*>(g_cvec)[hl];

#pragma unroll
    for (int p = 0; p < 4; p++) {
        const int gl = warp * 8 + p * 2 + half;  // local group 0..31
        const int g  = gbase + gl;

        int idx[MM];
#pragma unroll
        for (int m = 0; m < MM; m++) idx[m] = members[g * MM + m];
        const int ii = item_inputs[g];

        float4 r[MM];
#pragma unroll
        for (int m = 0; m < MM; m++) r[m] = ue4[(size_t)idx[m] * 16 + hl];
        const float4 t = ie4[(size_t)ii * 16 + hl];

        float4 e = r[0];
#pragma unroll
        for (int m = 1; m < MM; m++) {
            e.x += r[m].x; e.y += r[m].y; e.z += r[m].z; e.w += r[m].w;
        }

        reinterpret_cast<float4*>(&sEs[gl * TSS])[hl] = e;  // 272B row stride, 16B aligned
        reinterpret_cast<float4*>(&sTs[gl * TSS])[hl] = t;

        float cd = t.x * cv.x + t.y * cv.y + t.z * cv.z + t.w * cv.w;
#pragma unroll
        for (int off = 8; off; off >>= 1)
            cd += __shfl_xor_sync(0xffffffffu, cd, off);
        if (hl == 0) sCd[gl] = cd;
    }
    __syncthreads();

    // ---- GEMM phase: s[g,c] = sum_e Ts[g,e] * A[e,c] ----
    const int tx = tid & 15;          // c-tile: c0 = 4*tx
    const int ty = tid >> 4;          // 0..7, g-tile: g0 = 4*ty
    const int c0 = tx * 4, g0 = ty * 4;

    float s[4][4];
#pragma unroll
    for (int i = 0; i < 4; i++)
#pragma unroll
        for (int j = 0; j < 4; j++) s[i][j] = 0.f;

    const float4* A4 = reinterpret_cast<const float4*>(sA);
#pragma unroll
    for (int kc = 0; kc < DD; kc += 4) {
        float4 a[4];
#pragma unroll
        for (int kk = 0; kk < 4; kk++) a[kk] = A4[(kc + kk) * 16 + tx];
        float4 tg[4];
#pragma unroll
        for (int i = 0; i < 4; i++)
            tg[i] = *reinterpret_cast<const float4*>(&sTs[(g0 + i) * TSS + kc]);
#pragma unroll
        for (int i = 0; i < 4; i++) {
            const float tk0 = tg[i].x, tk1 = tg[i].y, tk2 = tg[i].z, tk3 = tg[i].w;
            s[i][0] = fmaf(tk0, a[0].x, s[i][0]); s[i][1] = fmaf(tk0, a[0].y, s[i][1]);
            s[i][2] = fmaf(tk0, a[0].z, s[i][2]); s[i][3] = fmaf(tk0, a[0].w, s[i][3]);
            s[i][0] = fmaf(tk1, a[1].x, s[i][0]); s[i][1] = fmaf(tk1, a[1].y, s[i][1]);
            s[i][2] = fmaf(tk1, a[1].z, s[i][2]); s[i][3] = fmaf(tk1, a[1].w, s[i][3]);
            s[i][0] = fmaf(tk2, a[2].x, s[i][0]); s[i][1] = fmaf(tk2, a[2].y, s[i][1]);
            s[i][2] = fmaf(tk2, a[2].z, s[i][2]); s[i][3] = fmaf(tk2, a[2].w, s[i][3]);
            s[i][0] = fmaf(tk3, a[3].x, s[i][0]); s[i][1] = fmaf(tk3, a[3].y, s[i][1]);
            s[i][2] = fmaf(tk3, a[3].z, s[i][2]); s[i][3] = fmaf(tk3, a[3].w, s[i][3]);
        }
    }

    // ---- Epilogue: y[g] = sum_c s[g,c]*Es[g,c] (+ cdot), reduce across 16 tx lanes ----
    float yp[4];
#pragma unroll
    for (int i = 0; i < 4; i++) {
        const float4 e = *reinterpret_cast<const float4*>(&sEs[(g0 + i) * TSS + c0]);
        yp[i] = s[i][0] * e.x + s[i][1] * e.y + s[i][2] * e.z + s[i][3] * e.w;
    }
#pragma unroll
    for (int off = 8; off; off >>= 1) {
#pragma unroll
        for (int i = 0; i < 4; i++)
            yp[i] += __shfl_xor_sync(0xffffffffu, yp[i], off);
    }
    if (tx == 0) {
#pragma unroll
        for (int i = 0; i < 4; i++)
            out[gbase + g0 + i] = yp[i] + sCd[g0 + i];
    }
}

extern "C" void kernel_launch(void* const* d_in, const int* in_sizes, int n_in,
                              void* d_out, int out_size) {
    // 0 user_emb, 1 quser_emb, 2 item_emb, 3 W_q, 4 b_q, 5 W_k, 6 b_k,
    // 7 W_v, 8 b_v, 9 W_o, 10 b_o, 11 w_t, 12 b_t, 13 members, 14 item_inputs
    const float* user_emb    = (const float*)d_in[0];
    const float* item_emb    = (const float*)d_in[2];
    const float* W_v         = (const float*)d_in[7];
    const float* b_v         = (const float*)d_in[8];
    const float* W_o         = (const float*)d_in[9];
    const float* b_o         = (const float*)d_in[10];
    const int*   members     = (const int*)d_in[13];
    const int*   item_inputs = (const int*)d_in[14];
    float* out = (float*)d_out;

    precompute_kernel<<<16, 256>>>(W_v, b_v, W_o, b_o);
    mosan_kernel<<<NBLK, 128>>>(user_emb, item_emb, members, item_inputs, out);
}